// round 8
// baseline (speedup 1.0000x reference)
#include <cuda_runtime.h>
#include <cuda_bf16.h>

#define NT 256              // 8 warps per CTA
#define PTS_PER_ITEM 64     // work item = (batch, 64-point chunk)
#define MAXPAIR 512         // q-pairs in shared (P<=1024)
#define NCTAS 456           // ~3 CTAs/SM; queue balances sym-heavy items dynamically
#define MARGIN 0.01f
#define FIXED_SCALE 4294967296.0

// Deterministic order-independent accumulator + completion counter + work queue.
// Zero-initialized; last CTA publishes and resets all three for graph replays.
__device__ long long    g_acc;
__device__ unsigned int g_count;
__device__ unsigned int g_work;

struct Rot { float r[9]; };

__device__ __forceinline__ Rot quat_rot(const float* __restrict__ q) {
    float s = q[0], u = q[1], v = q[2], w = q[3];
    Rot R;
    R.r[0] = 1.f - 2.f * (v * v + w * w);
    R.r[1] = 2.f * (u * v - s * w);
    R.r[2] = 2.f * (u * w + s * v);
    R.r[3] = 2.f * (u * v + s * w);
    R.r[4] = 1.f - 2.f * (u * u + w * w);
    R.r[5] = 2.f * (v * w - s * u);
    R.r[6] = 2.f * (u * w - s * v);
    R.r[7] = 2.f * (v * w + s * u);
    R.r[8] = 1.f - 2.f * (u * u + v * v);
    return R;
}

// ---- packed f32x2 helpers (Blackwell FFMA2) ----
__device__ __forceinline__ double ffma2(double a, double b, double c) {
    double d;
    asm("fma.rn.f32x2 %0, %1, %2, %3;" : "=d"(d) : "d"(a), "d"(b), "d"(c));
    return d;
}
__device__ __forceinline__ double splat2(float x) {
    double d;
    asm("mov.b64 %0, {%1, %1};" : "=d"(d) : "f"(x));
    return d;
}
__device__ __forceinline__ float lo32(double d) { return __int_as_float(__double2loint(d)); }
__device__ __forceinline__ float hi32(double d) { return __int_as_float(__double2hiint(d)); }

__global__ void __launch_bounds__(NT)
add_loss_kernel(const float* __restrict__ poses_pred,
                const float* __restrict__ poses_target,
                const int*   __restrict__ labels,
                const float* __restrict__ points,
                const int*   __restrict__ symmetry,
                float* __restrict__ out,
                int B, int C, int P, int S, int total_items)
{
    __shared__ float4 sA[MAXPAIR];   // (x_2j, x_2j+1, y_2j, y_2j+1)
    __shared__ float4 sB[MAXPAIR];   // (z_2j, z_2j+1, ||x2_2j||^2, ||x2_2j+1||^2)
    __shared__ float  smin[4 * PTS_PER_ITEM];
    __shared__ double swarp[NT / 32];
    __shared__ int    s_item;

    const int tid  = threadIdx.x;
    const int lane = tid & 31;
    const int wid  = tid >> 5;
    const int pl   = tid & 63;       // point-local index within item
    const int qc   = tid >> 6;       // q-quarter (0..3); constant per warp-pair -> LDS broadcast

    long long ll_acc = 0;            // tid 0 only

    for (;;) {
        if (tid == 0) s_item = (int)atomicAdd(&g_work, 1u);
        __syncthreads();
        const int item = s_item;
        if (item >= total_items) break;

        const int b     = item / S;
        const int chunk = item - b * S;
        const int label = labels[b];
        if (label <= 0) continue;    // block-uniform: all threads skip together

        const float* q1 = poses_pred   + ((size_t)b * C + label) * 4;
        const float* q2 = poses_target + ((size_t)b * C + label) * 4;
        Rot R1 = quat_rot(q1);
        Rot R2 = quat_rot(q2);
        const float* mp = points + (size_t)label * P * 3;
        const bool sym = symmetry[label] > 0;

        const int p = chunk * PTS_PER_ITEM + pl;
        double v = 0.0;

        if (!sym) {
            // ADD: threads 0..63 each handle one point
            if (tid < PTS_PER_ITEM && p < P) {
                float a = mp[3*p], bb = mp[3*p+1], c = mp[3*p+2];
                float x1x = R1.r[0]*a + R1.r[1]*bb + R1.r[2]*c;
                float x1y = R1.r[3]*a + R1.r[4]*bb + R1.r[5]*c;
                float x1z = R1.r[6]*a + R1.r[7]*bb + R1.r[8]*c;
                float x2x = R2.r[0]*a + R2.r[1]*bb + R2.r[2]*c;
                float x2y = R2.r[3]*a + R2.r[4]*bb + R2.r[5]*c;
                float x2z = R2.r[6]*a + R2.r[7]*bb + R2.r[8]*c;
                float dx = x1x - x2x, dy = x1y - x2y, dz = x1z - x2z;
                float d = dx*dx + dy*dy + dz*dz;
                v = (double)fmaxf(0.5f * d - MARGIN, 0.f);
            }
        } else {
            const int npairs = P >> 1;
            // fill full x2 tile as q-pairs (512 pairs / 256 threads = 2 iters)
            for (int j = tid; j < npairs; j += NT) {
                int qa = 2 * j, qb = 2 * j + 1;
                float a0 = mp[3*qa], b0 = mp[3*qa+1], c0 = mp[3*qa+2];
                float a1 = mp[3*qb], b1 = mp[3*qb+1], c1 = mp[3*qb+2];
                float x0 = R2.r[0]*a0 + R2.r[1]*b0 + R2.r[2]*c0;
                float y0 = R2.r[3]*a0 + R2.r[4]*b0 + R2.r[5]*c0;
                float z0 = R2.r[6]*a0 + R2.r[7]*b0 + R2.r[8]*c0;
                float x1 = R2.r[0]*a1 + R2.r[1]*b1 + R2.r[2]*c1;
                float y1 = R2.r[3]*a1 + R2.r[4]*b1 + R2.r[5]*c1;
                float z1 = R2.r[6]*a1 + R2.r[7]*b1 + R2.r[8]*c1;
                sA[j] = make_float4(x0, x1, y0, y1);
                sB[j] = make_float4(z0, z1,
                                    x0*x0 + y0*y0 + z0*z0,
                                    x1*x1 + y1*y1 + z1*z1);
            }
            __syncthreads();

            // per-thread: x1 of point p (computed redundantly by the 4 qc groups)
            float n1 = 0.f;
            double Ax = splat2(0.f), Ay = Ax, Az = Ax;
            if (p < P) {
                float a = mp[3*p], bb = mp[3*p+1], c = mp[3*p+2];
                float x = R1.r[0]*a + R1.r[1]*bb + R1.r[2]*c;
                float y = R1.r[3]*a + R1.r[4]*bb + R1.r[5]*c;
                float z = R1.r[6]*a + R1.r[7]*bb + R1.r[8]*c;
                Ax = splat2(-2.f*x); Ay = splat2(-2.f*y); Az = splat2(-2.f*z);
                n1 = x*x + y*y + z*z;
            }

            // q-quarter loop: lanes of a warp share qc -> pure broadcast LDS
            const int q4 = (npairs + 3) >> 2;
            const int j0 = qc * q4;
            const int j1 = (j0 + q4 < npairs) ? (j0 + q4) : npairs;
            const float INF = 3.4028235e38f;
            float m0 = INF, m1 = INF;
            const double2* __restrict__ pA = (const double2*)sA;
            const double2* __restrict__ pB = (const double2*)sB;
            #pragma unroll 4
            for (int j = j0; j < j1; j++) {
                double2 v1 = pA[j];
                double2 v2 = pB[j];
                double t = ffma2(Ax, v1.x, ffma2(Ay, v1.y, ffma2(Az, v2.x, v2.y)));
                m0 = fminf(m0, lo32(t));
                m1 = fminf(m1, hi32(t));
            }
            smin[qc * PTS_PER_ITEM + pl] = fminf(m0, m1);
            __syncthreads();

            if (tid < PTS_PER_ITEM && p < P) {
                float mn = fminf(fminf(smin[tid],                    smin[PTS_PER_ITEM + tid]),
                                 fminf(smin[2*PTS_PER_ITEM + tid],   smin[3*PTS_PER_ITEM + tid]));
                v = (double)fmaxf(0.5f * (n1 + mn) - MARGIN, 0.f);
            }
        }

        // ---- per-item block reduction (fixed order -> partition-independent) ----
        #pragma unroll
        for (int off = 16; off > 0; off >>= 1)
            v += __shfl_down_sync(0xFFFFFFFFu, v, off);
        if (lane == 0) swarp[wid] = v;
        __syncthreads();
        if (tid == 0) {
            double isum = 0.0;
            #pragma unroll
            for (int w = 0; w < NT / 32; w++) isum += swarp[w];
            ll_acc += (long long)llrint(isum * FIXED_SCALE);
        }
        __syncthreads();   // protect swarp/sA before next item
    }

    if (tid == 0) {
        if (ll_acc != 0) atomicAdd((unsigned long long*)&g_acc, (unsigned long long)ll_acc);
        __threadfence();
        unsigned int prev = atomicAdd(&g_count, 1u);
        if (prev == gridDim.x - 1) {
            long long acc = (long long)atomicAdd((unsigned long long*)&g_acc, 0ull);
            out[0] = (float)(((double)acc / FIXED_SCALE) / ((double)B * (double)P));
            g_acc  = 0;
            g_count = 0;
            g_work  = 0;
            __threadfence();
        }
    }
}

extern "C" void kernel_launch(void* const* d_in, const int* in_sizes, int n_in,
                              void* d_out, int out_size)
{
    const float* poses_pred   = (const float*)d_in[0];
    const float* poses_target = (const float*)d_in[1];
    const int*   poses_labels = (const int*)d_in[2];
    const float* points       = (const float*)d_in[3];
    const int*   symmetry     = (const int*)d_in[4];
    float* out = (float*)d_out;

    const int B = in_sizes[2];                 // labels: [B]
    const int C = in_sizes[4];                 // symmetry: [C]
    const int P = in_sizes[3] / (C * 3);       // points: [C,P,3]
    const int S = (P + PTS_PER_ITEM - 1) / PTS_PER_ITEM;
    const int total_items = B * S;

    add_loss_kernel<<<NCTAS, NT>>>(poses_pred, poses_target, poses_labels,
                                   points, symmetry, out, B, C, P, S, total_items);
}

// round 9
// speedup vs baseline: 1.4318x; 1.4318x over previous
#include <cuda_runtime.h>
#include <cuda_bf16.h>

#define NTM 128             // main kernel threads
#define NTF 256             // finalize kernel threads
#define QC  128             // q's per chunk (per CTA)
#define NPAIR (QC / 2)      // 64 q-pairs in shared
#define PPT 8               // points per thread (128*8 = full P)
#define MARGIN 0.01f
#define FIXED_SCALE 4294967296.0
#define MAXBP (128 * 1024)

// Scratch: per-(b,p) running min, encoded so that 0 == +inf and unsigned MAX
// == float MIN (monotone-decreasing key). Zero-init static state is therefore
// already "empty"; finalize resets entries to 0 after reading, keeping every
// graph replay clean. atomicMax on the key is exact & order-independent.
__device__ unsigned int g_keys[MAXBP];
__device__ long long    g_acc;     // fixed-point deterministic sum
__device__ unsigned int g_count;   // finalize completion counter

struct Rot { float r[9]; };

__device__ __forceinline__ Rot quat_rot(const float* __restrict__ q) {
    float s = q[0], u = q[1], v = q[2], w = q[3];
    Rot R;
    R.r[0] = 1.f - 2.f * (v * v + w * w);
    R.r[1] = 2.f * (u * v - s * w);
    R.r[2] = 2.f * (u * w + s * v);
    R.r[3] = 2.f * (u * v + s * w);
    R.r[4] = 1.f - 2.f * (u * u + w * w);
    R.r[5] = 2.f * (v * w - s * u);
    R.r[6] = 2.f * (u * w - s * v);
    R.r[7] = 2.f * (v * w + s * u);
    R.r[8] = 1.f - 2.f * (u * u + v * v);
    return R;
}

// ---- packed f32x2 helpers (Blackwell FFMA2) ----
__device__ __forceinline__ double ffma2(double a, double b, double c) {
    double d;
    asm("fma.rn.f32x2 %0, %1, %2, %3;" : "=d"(d) : "d"(a), "d"(b), "d"(c));
    return d;
}
__device__ __forceinline__ double splat2(float x) {
    double d;
    asm("mov.b64 %0, {%1, %1};" : "=d"(d) : "f"(x));
    return d;
}
__device__ __forceinline__ float lo32(double d) { return __int_as_float(__double2loint(d)); }
__device__ __forceinline__ float hi32(double d) { return __int_as_float(__double2hiint(d)); }

// monotone-DEcreasing float->uint key: max(key) == min(float); key 0 == +inf
__device__ __forceinline__ unsigned int kk_of(float f) {
    unsigned int u = __float_as_uint(f);
    unsigned int k = (u & 0x80000000u) ? ~u : (u | 0x80000000u);  // increasing
    return ~k;                                                    // decreasing
}

__global__ void __launch_bounds__(NTM)
main_kernel(const float* __restrict__ poses_pred,
            const float* __restrict__ poses_target,
            const int*   __restrict__ labels,
            const float* __restrict__ points,
            const int*   __restrict__ symmetry,
            int B, int C, int P)
{
    const int b   = blockIdx.x;
    const int yc  = blockIdx.y;        // q-chunk index
    const int tid = threadIdx.x;

    const int label = labels[b];
    if (label <= 0) return;
    const bool sym = symmetry[label] > 0;

    const float* mp = points + (size_t)label * P * 3;
    Rot R1 = quat_rot(poses_pred   + ((size_t)b * C + label) * 4);
    Rot R2 = quat_rot(poses_target + ((size_t)b * C + label) * 4);

    if (!sym) {
        // ADD handled once (chunk 0 only), 8 points/thread, direct fixed-point sum
        if (yc != 0) return;
        __shared__ double swarp[NTM / 32];
        double v = 0.0;
        #pragma unroll
        for (int k = 0; k < PPT; k++) {
            int p = k * NTM + tid;
            if (p < P) {
                float a = mp[3*p], bb = mp[3*p+1], c = mp[3*p+2];
                float x1x = R1.r[0]*a + R1.r[1]*bb + R1.r[2]*c;
                float x1y = R1.r[3]*a + R1.r[4]*bb + R1.r[5]*c;
                float x1z = R1.r[6]*a + R1.r[7]*bb + R1.r[8]*c;
                float x2x = R2.r[0]*a + R2.r[1]*bb + R2.r[2]*c;
                float x2y = R2.r[3]*a + R2.r[4]*bb + R2.r[5]*c;
                float x2z = R2.r[6]*a + R2.r[7]*bb + R2.r[8]*c;
                float dx = x1x - x2x, dy = x1y - x2y, dz = x1z - x2z;
                float d = dx*dx + dy*dy + dz*dz;
                v += (double)fmaxf(0.5f * d - MARGIN, 0.f);
            }
        }
        const int lane = tid & 31, wid = tid >> 5;
        #pragma unroll
        for (int off = 16; off > 0; off >>= 1)
            v += __shfl_down_sync(0xFFFFFFFFu, v, off);
        if (lane == 0) swarp[wid] = v;
        __syncthreads();
        if (tid == 0) {
            double bsum = 0.0;
            #pragma unroll
            for (int w = 0; w < NTM / 32; w++) bsum += swarp[w];
            long long contrib = (long long)llrint(bsum * FIXED_SCALE);
            if (contrib != 0)
                atomicAdd((unsigned long long*)&g_acc, (unsigned long long)contrib);
        }
        return;
    }

    // ---- ADD-S: this CTA handles q-range [yc*QC, yc*QC+QC) for ALL P points ----
    __shared__ float4 sA[NPAIR];   // (x_2j, x_2j+1, y_2j, y_2j+1)
    __shared__ float4 sB[NPAIR];   // (z_2j, z_2j+1, n2_2j, n2_2j+1)

    const int q0 = yc * QC;
    const int npr = min(NPAIR, (P - q0) >> 1);
    for (int j = tid; j < npr; j += NTM) {
        int qa = q0 + 2 * j, qb = qa + 1;
        float a0 = mp[3*qa], b0 = mp[3*qa+1], c0 = mp[3*qa+2];
        float a1 = mp[3*qb], b1 = mp[3*qb+1], c1 = mp[3*qb+2];
        float x0 = R2.r[0]*a0 + R2.r[1]*b0 + R2.r[2]*c0;
        float y0 = R2.r[3]*a0 + R2.r[4]*b0 + R2.r[5]*c0;
        float z0 = R2.r[6]*a0 + R2.r[7]*b0 + R2.r[8]*c0;
        float x1 = R2.r[0]*a1 + R2.r[1]*b1 + R2.r[2]*c1;
        float y1 = R2.r[3]*a1 + R2.r[4]*b1 + R2.r[5]*c1;
        float z1 = R2.r[6]*a1 + R2.r[7]*b1 + R2.r[8]*c1;
        sA[j] = make_float4(x0, x1, y0, y1);
        sB[j] = make_float4(z0, z1,
                            x0*x0 + y0*y0 + z0*z0,
                            x1*x1 + y1*y1 + z1*z1);
    }
    __syncthreads();

    // 8 points per thread: splat -2*x1 once
    float  n1v[PPT];
    double Ax[PPT], Ay[PPT], Az[PPT];
    #pragma unroll
    for (int k = 0; k < PPT; k++) {
        int p = k * NTM + tid;
        float a = 0.f, bb = 0.f, c = 0.f;
        if (p < P) { a = mp[3*p]; bb = mp[3*p+1]; c = mp[3*p+2]; }
        float x = R1.r[0]*a + R1.r[1]*bb + R1.r[2]*c;
        float y = R1.r[3]*a + R1.r[4]*bb + R1.r[5]*c;
        float z = R1.r[6]*a + R1.r[7]*bb + R1.r[8]*c;
        Ax[k] = splat2(-2.f*x); Ay[k] = splat2(-2.f*y); Az[k] = splat2(-2.f*z);
        n1v[k] = x*x + y*y + z*z;
    }

    const float INF = 3.4028235e38f;
    float m0[PPT], m1[PPT];
    #pragma unroll
    for (int k = 0; k < PPT; k++) { m0[k] = INF; m1[k] = INF; }

    // inner loop: 2 LDS.128 feed 8 points -> 0.125 LDS per pq-product
    const double2* __restrict__ pA = (const double2*)sA;
    const double2* __restrict__ pB = (const double2*)sB;
    #pragma unroll 2
    for (int j = 0; j < npr; j++) {
        double2 v1 = pA[j];
        double2 v2 = pB[j];
        #pragma unroll
        for (int k = 0; k < PPT; k++) {
            double t = ffma2(Ax[k], v1.x, ffma2(Ay[k], v1.y, ffma2(Az[k], v2.x, v2.y)));
            m0[k] = fminf(m0[k], lo32(t));
            m1[k] = fminf(m1[k], hi32(t));
        }
    }

    // fold n1 and publish per-(b,p) partial min (exact, order-independent)
    #pragma unroll
    for (int k = 0; k < PPT; k++) {
        int p = k * NTM + tid;
        if (p < P) {
            float d = n1v[k] + fminf(m0[k], m1[k]);
            atomicMax(&g_keys[(size_t)b * P + p], kk_of(d));
        }
    }
}

__global__ void __launch_bounds__(NTF)
finalize_kernel(float* __restrict__ out, int n, int B, int P)
{
    __shared__ double swarp[NTF / 32];
    const int i    = blockIdx.x * NTF + threadIdx.x;
    const int tid  = threadIdx.x;
    const int lane = tid & 31, wid = tid >> 5;

    double v = 0.0;
    if (i < n) {
        unsigned int kk = g_keys[i];
        if (kk != 0u) {
            g_keys[i] = 0u;                          // reset for next replay
            unsigned int k = ~kk;
            unsigned int u = (k & 0x80000000u) ? (k ^ 0x80000000u) : ~k;
            float d = __uint_as_float(u);
            v = (double)fmaxf(0.5f * d - MARGIN, 0.f);
        }
    }

    #pragma unroll
    for (int off = 16; off > 0; off >>= 1)
        v += __shfl_down_sync(0xFFFFFFFFu, v, off);
    if (lane == 0) swarp[wid] = v;
    __syncthreads();

    if (tid == 0) {
        double bsum = 0.0;
        #pragma unroll
        for (int w = 0; w < NTF / 32; w++) bsum += swarp[w];
        long long contrib = (long long)llrint(bsum * FIXED_SCALE);
        if (contrib != 0)
            atomicAdd((unsigned long long*)&g_acc, (unsigned long long)contrib);
        __threadfence();

        unsigned int prev = atomicAdd(&g_count, 1u);
        if (prev == gridDim.x - 1) {
            long long acc = (long long)atomicAdd((unsigned long long*)&g_acc, 0ull);
            out[0] = (float)(((double)acc / FIXED_SCALE) / ((double)B * (double)P));
            g_acc = 0;
            g_count = 0;
            __threadfence();
        }
    }
}

extern "C" void kernel_launch(void* const* d_in, const int* in_sizes, int n_in,
                              void* d_out, int out_size)
{
    const float* poses_pred   = (const float*)d_in[0];
    const float* poses_target = (const float*)d_in[1];
    const int*   poses_labels = (const int*)d_in[2];
    const float* points       = (const float*)d_in[3];
    const int*   symmetry     = (const int*)d_in[4];
    float* out = (float*)d_out;

    const int B = in_sizes[2];                 // labels: [B]
    const int C = in_sizes[4];                 // symmetry: [C]
    const int P = in_sizes[3] / (C * 3);       // points: [C,P,3]
    const int S = (P + QC - 1) / QC;           // q-chunks per batch

    dim3 grid(B, S);
    main_kernel<<<grid, NTM>>>(poses_pred, poses_target, poses_labels,
                               points, symmetry, B, C, P);

    const int n = B * P;
    const int fblocks = (n + NTF - 1) / NTF;
    finalize_kernel<<<fblocks, NTF>>>(out, n, B, P);
}

// round 10
// speedup vs baseline: 1.7181x; 1.2000x over previous
#include <cuda_runtime.h>
#include <cuda_bf16.h>

#define NT 128              // threads per CTA
#define QC 128              // q's per work item
#define NPAIR (QC / 2)      // 64 q-pairs in shared
#define PPT 8               // points per thread (128*8 = 1024 = P)
#define NCTAS 592           // persistent CTAs, ~4/SM, pull items from queue
#define MARGIN 0.01f
#define FIXED_SCALE 4294967296.0
#define MAXBP (128 * 1024)
#define MAXB 1024

// Exact, order-independent state. Zero-init at load; every piece is reset by
// its consumer, so graph replays always start clean.
__device__ unsigned int g_keys[MAXBP];   // per-(b,p) min key; 0 == +inf
__device__ unsigned int g_bdone[MAXB];   // per-batch completed q-chunks
__device__ long long    g_acc;           // fixed-point deterministic loss sum
__device__ unsigned int g_count;         // CTA completion counter
__device__ unsigned int g_work;          // work queue head

struct Rot { float r[9]; };

__device__ __forceinline__ Rot quat_rot(const float* __restrict__ q) {
    float s = q[0], u = q[1], v = q[2], w = q[3];
    Rot R;
    R.r[0] = 1.f - 2.f * (v * v + w * w);
    R.r[1] = 2.f * (u * v - s * w);
    R.r[2] = 2.f * (u * w + s * v);
    R.r[3] = 2.f * (u * v + s * w);
    R.r[4] = 1.f - 2.f * (u * u + w * w);
    R.r[5] = 2.f * (v * w - s * u);
    R.r[6] = 2.f * (u * w - s * v);
    R.r[7] = 2.f * (v * w + s * u);
    R.r[8] = 1.f - 2.f * (u * u + v * v);
    return R;
}

// ---- packed f32x2 helpers (Blackwell FFMA2) ----
__device__ __forceinline__ double ffma2(double a, double b, double c) {
    double d;
    asm("fma.rn.f32x2 %0, %1, %2, %3;" : "=d"(d) : "d"(a), "d"(b), "d"(c));
    return d;
}
__device__ __forceinline__ double splat2(float x) {
    double d;
    asm("mov.b64 %0, {%1, %1};" : "=d"(d) : "f"(x));
    return d;
}
__device__ __forceinline__ float lo32(double d) { return __int_as_float(__double2loint(d)); }
__device__ __forceinline__ float hi32(double d) { return __int_as_float(__double2hiint(d)); }

// monotone-DEcreasing float->uint key: max(key) == min(float); key 0 == +inf
__device__ __forceinline__ unsigned int kk_of(float f) {
    unsigned int u = __float_as_uint(f);
    unsigned int k = (u & 0x80000000u) ? ~u : (u | 0x80000000u);
    return ~k;
}
__device__ __forceinline__ float f_of_kk(unsigned int kk) {
    unsigned int k = ~kk;
    unsigned int u = (k & 0x80000000u) ? (k ^ 0x80000000u) : ~k;
    return __uint_as_float(u);
}

__global__ void __launch_bounds__(NT)
add_loss_kernel(const float* __restrict__ poses_pred,
                const float* __restrict__ poses_target,
                const int*   __restrict__ labels,
                const float* __restrict__ points,
                const int*   __restrict__ symmetry,
                float* __restrict__ out,
                int B, int C, int P, int S, int total_items)
{
    __shared__ float4 sA[NPAIR];          // (x_2j, x_2j+1, y_2j, y_2j+1)
    __shared__ float4 sB[NPAIR];          // (z_2j, z_2j+1, n2_2j, n2_2j+1)
    __shared__ double swarp[NT / 32];
    __shared__ int    s_item;
    __shared__ int    s_last;

    const int tid  = threadIdx.x;
    const int lane = tid & 31;
    const int wid  = tid >> 5;

    long long ll_acc = 0;                 // tid 0 only

    for (;;) {
        if (tid == 0) s_item = (int)atomicAdd(&g_work, 1u);
        __syncthreads();                  // also fences smem reuse across items
        const int item = s_item;
        if (item >= total_items) break;

        const int b  = item / S;
        const int yc = item - b * S;
        const int label = labels[b];
        if (label <= 0) continue;         // block-uniform skip

        const bool sym = symmetry[label] > 0;
        const float* mp = points + (size_t)label * P * 3;
        Rot R1 = quat_rot(poses_pred   + ((size_t)b * C + label) * 4);
        Rot R2 = quat_rot(poses_target + ((size_t)b * C + label) * 4);

        if (!sym) {
            if (yc != 0) continue;        // ADD done entirely by chunk-0 item
            double v = 0.0;
            #pragma unroll
            for (int k = 0; k < PPT; k++) {
                int p = k * NT + tid;
                if (p < P) {
                    float a = mp[3*p], bb = mp[3*p+1], c = mp[3*p+2];
                    float x1x = R1.r[0]*a + R1.r[1]*bb + R1.r[2]*c;
                    float x1y = R1.r[3]*a + R1.r[4]*bb + R1.r[5]*c;
                    float x1z = R1.r[6]*a + R1.r[7]*bb + R1.r[8]*c;
                    float x2x = R2.r[0]*a + R2.r[1]*bb + R2.r[2]*c;
                    float x2y = R2.r[3]*a + R2.r[4]*bb + R2.r[5]*c;
                    float x2z = R2.r[6]*a + R2.r[7]*bb + R2.r[8]*c;
                    float dx = x1x - x2x, dy = x1y - x2y, dz = x1z - x2z;
                    float d = dx*dx + dy*dy + dz*dz;
                    v += (double)fmaxf(0.5f * d - MARGIN, 0.f);
                }
            }
            #pragma unroll
            for (int off = 16; off > 0; off >>= 1)
                v += __shfl_down_sync(0xFFFFFFFFu, v, off);
            if (lane == 0) swarp[wid] = v;
            __syncthreads();
            if (tid == 0) {
                double bsum = 0.0;
                #pragma unroll
                for (int w = 0; w < NT / 32; w++) bsum += swarp[w];
                ll_acc += (long long)llrint(bsum * FIXED_SCALE);
            }
            continue;
        }

        // ---- ADD-S item: q-range [yc*QC, yc*QC+QC) x ALL P points ----
        const int q0 = yc * QC;
        const int npr = min(NPAIR, (P - q0) >> 1);
        for (int j = tid; j < npr; j += NT) {
            int qa = q0 + 2 * j, qb = qa + 1;
            float a0 = mp[3*qa], b0 = mp[3*qa+1], c0 = mp[3*qa+2];
            float a1 = mp[3*qb], b1 = mp[3*qb+1], c1 = mp[3*qb+2];
            float x0 = R2.r[0]*a0 + R2.r[1]*b0 + R2.r[2]*c0;
            float y0 = R2.r[3]*a0 + R2.r[4]*b0 + R2.r[5]*c0;
            float z0 = R2.r[6]*a0 + R2.r[7]*b0 + R2.r[8]*c0;
            float x1 = R2.r[0]*a1 + R2.r[1]*b1 + R2.r[2]*c1;
            float y1 = R2.r[3]*a1 + R2.r[4]*b1 + R2.r[5]*c1;
            float z1 = R2.r[6]*a1 + R2.r[7]*b1 + R2.r[8]*c1;
            sA[j] = make_float4(x0, x1, y0, y1);
            sB[j] = make_float4(z0, z1,
                                x0*x0 + y0*y0 + z0*z0,
                                x1*x1 + y1*y1 + z1*z1);
        }
        __syncthreads();

        float  n1v[PPT];
        double Ax[PPT], Ay[PPT], Az[PPT];
        #pragma unroll
        for (int k = 0; k < PPT; k++) {
            int p = k * NT + tid;
            float a = 0.f, bb = 0.f, c = 0.f;
            if (p < P) { a = mp[3*p]; bb = mp[3*p+1]; c = mp[3*p+2]; }
            float x = R1.r[0]*a + R1.r[1]*bb + R1.r[2]*c;
            float y = R1.r[3]*a + R1.r[4]*bb + R1.r[5]*c;
            float z = R1.r[6]*a + R1.r[7]*bb + R1.r[8]*c;
            Ax[k] = splat2(-2.f*x); Ay[k] = splat2(-2.f*y); Az[k] = splat2(-2.f*z);
            n1v[k] = x*x + y*y + z*z;
        }

        const float INF = 3.4028235e38f;
        float m0[PPT], m1[PPT];
        #pragma unroll
        for (int k = 0; k < PPT; k++) { m0[k] = INF; m1[k] = INF; }

        const double2* __restrict__ pA = (const double2*)sA;
        const double2* __restrict__ pB = (const double2*)sB;
        #pragma unroll 2
        for (int j = 0; j < npr; j++) {
            double2 v1 = pA[j];
            double2 v2 = pB[j];
            #pragma unroll
            for (int k = 0; k < PPT; k++) {
                double t = ffma2(Ax[k], v1.x, ffma2(Ay[k], v1.y, ffma2(Az[k], v2.x, v2.y)));
                m0[k] = fminf(m0[k], lo32(t));
                m1[k] = fminf(m1[k], hi32(t));
            }
        }

        #pragma unroll
        for (int k = 0; k < PPT; k++) {
            int p = k * NT + tid;
            if (p < P) {
                float d = n1v[k] + fminf(m0[k], m1[k]);
                atomicMax(&g_keys[(size_t)b * P + p], kk_of(d));
            }
        }
        __threadfence();

        // per-batch completion: last of S chunk-items finalizes this batch inline
        if (tid == 0)
            s_last = (atomicAdd(&g_bdone[b], 1u) == (unsigned)(S - 1)) ? 1 : 0;
        __syncthreads();

        if (s_last) {
            double v = 0.0;
            #pragma unroll
            for (int k = 0; k < PPT; k++) {
                int p = k * NT + tid;
                if (p < P) {
                    size_t idx = (size_t)b * P + p;
                    unsigned int kk = g_keys[idx];
                    g_keys[idx] = 0u;                    // reset for next replay
                    v += (double)fmaxf(0.5f * f_of_kk(kk) - MARGIN, 0.f);
                }
            }
            #pragma unroll
            for (int off = 16; off > 0; off >>= 1)
                v += __shfl_down_sync(0xFFFFFFFFu, v, off);
            if (lane == 0) swarp[wid] = v;
            __syncthreads();
            if (tid == 0) {
                double bsum = 0.0;
                #pragma unroll
                for (int w = 0; w < NT / 32; w++) bsum += swarp[w];
                ll_acc += (long long)llrint(bsum * FIXED_SCALE);
                g_bdone[b] = 0u;                         // reset for next replay
            }
        }
    }

    // ---- CTA exit: contribute, then last CTA publishes & resets ----
    if (tid == 0) {
        if (ll_acc != 0)
            atomicAdd((unsigned long long*)&g_acc, (unsigned long long)ll_acc);
        __threadfence();
        unsigned int prev = atomicAdd(&g_count, 1u);
        if (prev == gridDim.x - 1) {
            long long acc = (long long)atomicAdd((unsigned long long*)&g_acc, 0ull);
            out[0] = (float)(((double)acc / FIXED_SCALE) / ((double)B * (double)P));
            g_acc  = 0;
            g_count = 0;
            g_work  = 0;
            __threadfence();
        }
    }
}

extern "C" void kernel_launch(void* const* d_in, const int* in_sizes, int n_in,
                              void* d_out, int out_size)
{
    const float* poses_pred   = (const float*)d_in[0];
    const float* poses_target = (const float*)d_in[1];
    const int*   poses_labels = (const int*)d_in[2];
    const float* points       = (const float*)d_in[3];
    const int*   symmetry     = (const int*)d_in[4];
    float* out = (float*)d_out;

    const int B = in_sizes[2];                 // labels: [B]
    const int C = in_sizes[4];                 // symmetry: [C]
    const int P = in_sizes[3] / (C * 3);       // points: [C,P,3]
    const int S = (P + QC - 1) / QC;           // q-chunks per batch
    const int total_items = B * S;

    add_loss_kernel<<<NCTAS, NT>>>(poses_pred, poses_target, poses_labels,
                                   points, symmetry, out, B, C, P, S, total_items);
}

// round 11
// speedup vs baseline: 1.7323x; 1.0083x over previous
#include <cuda_runtime.h>
#include <cuda_bf16.h>

#define NT 128              // threads per CTA
#define QC 64               // q's per work item (fine grain for queue balance)
#define NPAIR (QC / 2)      // 32 q-pairs in shared
#define PPT 8               // points per thread (128*8 = 1024 = P)
#define NCTAS 888           // persistent CTAs, 6/SM (regs allow 7)
#define MARGIN 0.01f
#define FIXED_SCALE 4294967296.0
#define MAXBP (128 * 1024)
#define MAXB 1024

// Exact, order-independent state. Zero-init at load; every piece is reset by
// its consumer, so graph replays always start clean.
__device__ unsigned int g_keys[MAXBP];   // per-(b,p) min key; 0 == +inf
__device__ unsigned int g_bdone[MAXB];   // per-batch completed q-chunks
__device__ long long    g_acc;           // fixed-point deterministic loss sum
__device__ unsigned int g_count;         // CTA completion counter
__device__ unsigned int g_work;          // work queue head

struct Rot { float r[9]; };

__device__ __forceinline__ Rot quat_rot(const float* __restrict__ q) {
    float s = q[0], u = q[1], v = q[2], w = q[3];
    Rot R;
    R.r[0] = 1.f - 2.f * (v * v + w * w);
    R.r[1] = 2.f * (u * v - s * w);
    R.r[2] = 2.f * (u * w + s * v);
    R.r[3] = 2.f * (u * v + s * w);
    R.r[4] = 1.f - 2.f * (u * u + w * w);
    R.r[5] = 2.f * (v * w - s * u);
    R.r[6] = 2.f * (u * w - s * v);
    R.r[7] = 2.f * (v * w + s * u);
    R.r[8] = 1.f - 2.f * (u * u + v * v);
    return R;
}

// ---- packed f32x2 helpers (Blackwell FFMA2) ----
__device__ __forceinline__ double ffma2(double a, double b, double c) {
    double d;
    asm("fma.rn.f32x2 %0, %1, %2, %3;" : "=d"(d) : "d"(a), "d"(b), "d"(c));
    return d;
}
__device__ __forceinline__ double splat2(float x) {
    double d;
    asm("mov.b64 %0, {%1, %1};" : "=d"(d) : "f"(x));
    return d;
}
__device__ __forceinline__ float lo32(double d) { return __int_as_float(__double2loint(d)); }
__device__ __forceinline__ float hi32(double d) { return __int_as_float(__double2hiint(d)); }

// monotone-DEcreasing float->uint key: max(key) == min(float); key 0 == +inf
__device__ __forceinline__ unsigned int kk_of(float f) {
    unsigned int u = __float_as_uint(f);
    unsigned int k = (u & 0x80000000u) ? ~u : (u | 0x80000000u);
    return ~k;
}
__device__ __forceinline__ float f_of_kk(unsigned int kk) {
    unsigned int k = ~kk;
    unsigned int u = (k & 0x80000000u) ? (k ^ 0x80000000u) : ~k;
    return __uint_as_float(u);
}

__global__ void __launch_bounds__(NT)
add_loss_kernel(const float* __restrict__ poses_pred,
                const float* __restrict__ poses_target,
                const int*   __restrict__ labels,
                const float* __restrict__ points,
                const int*   __restrict__ symmetry,
                float* __restrict__ out,
                int B, int C, int P, int S, int total_items)
{
    __shared__ float4 sA[NPAIR];          // (x_2j, x_2j+1, y_2j, y_2j+1)
    __shared__ float4 sB[NPAIR];          // (z_2j, z_2j+1, n2_2j, n2_2j+1)
    __shared__ double swarp[NT / 32];
    __shared__ int    s_item;
    __shared__ int    s_last;

    const int tid  = threadIdx.x;
    const int lane = tid & 31;
    const int wid  = tid >> 5;

    long long ll_acc = 0;                 // tid 0 only

    for (;;) {
        if (tid == 0) s_item = (int)atomicAdd(&g_work, 1u);
        __syncthreads();                  // also fences smem reuse across items
        const int item = s_item;
        if (item >= total_items) break;

        const int b  = item / S;
        const int yc = item - b * S;
        const int label = labels[b];
        if (label <= 0) continue;         // block-uniform skip

        const bool sym = symmetry[label] > 0;
        const float* mp = points + (size_t)label * P * 3;
        Rot R1 = quat_rot(poses_pred   + ((size_t)b * C + label) * 4);
        Rot R2 = quat_rot(poses_target + ((size_t)b * C + label) * 4);

        if (!sym) {
            if (yc != 0) continue;        // ADD done entirely by chunk-0 item
            double v = 0.0;
            #pragma unroll
            for (int k = 0; k < PPT; k++) {
                int p = k * NT + tid;
                if (p < P) {
                    float a = mp[3*p], bb = mp[3*p+1], c = mp[3*p+2];
                    float x1x = R1.r[0]*a + R1.r[1]*bb + R1.r[2]*c;
                    float x1y = R1.r[3]*a + R1.r[4]*bb + R1.r[5]*c;
                    float x1z = R1.r[6]*a + R1.r[7]*bb + R1.r[8]*c;
                    float x2x = R2.r[0]*a + R2.r[1]*bb + R2.r[2]*c;
                    float x2y = R2.r[3]*a + R2.r[4]*bb + R2.r[5]*c;
                    float x2z = R2.r[6]*a + R2.r[7]*bb + R2.r[8]*c;
                    float dx = x1x - x2x, dy = x1y - x2y, dz = x1z - x2z;
                    float d = dx*dx + dy*dy + dz*dz;
                    v += (double)fmaxf(0.5f * d - MARGIN, 0.f);
                }
            }
            #pragma unroll
            for (int off = 16; off > 0; off >>= 1)
                v += __shfl_down_sync(0xFFFFFFFFu, v, off);
            if (lane == 0) swarp[wid] = v;
            __syncthreads();
            if (tid == 0) {
                double bsum = 0.0;
                #pragma unroll
                for (int w = 0; w < NT / 32; w++) bsum += swarp[w];
                ll_acc += (long long)llrint(bsum * FIXED_SCALE);
            }
            continue;
        }

        // ---- ADD-S item: q-range [yc*QC, yc*QC+QC) x ALL P points ----
        const int q0 = yc * QC;
        const int npr = min(NPAIR, (P - q0) >> 1);
        if (tid < npr) {
            int j = tid;
            int qa = q0 + 2 * j, qb = qa + 1;
            float a0 = mp[3*qa], b0 = mp[3*qa+1], c0 = mp[3*qa+2];
            float a1 = mp[3*qb], b1 = mp[3*qb+1], c1 = mp[3*qb+2];
            float x0 = R2.r[0]*a0 + R2.r[1]*b0 + R2.r[2]*c0;
            float y0 = R2.r[3]*a0 + R2.r[4]*b0 + R2.r[5]*c0;
            float z0 = R2.r[6]*a0 + R2.r[7]*b0 + R2.r[8]*c0;
            float x1 = R2.r[0]*a1 + R2.r[1]*b1 + R2.r[2]*c1;
            float y1 = R2.r[3]*a1 + R2.r[4]*b1 + R2.r[5]*c1;
            float z1 = R2.r[6]*a1 + R2.r[7]*b1 + R2.r[8]*c1;
            sA[j] = make_float4(x0, x1, y0, y1);
            sB[j] = make_float4(z0, z1,
                                x0*x0 + y0*y0 + z0*z0,
                                x1*x1 + y1*y1 + z1*z1);
        }
        __syncthreads();

        float  n1v[PPT];
        double Ax[PPT], Ay[PPT], Az[PPT];
        #pragma unroll
        for (int k = 0; k < PPT; k++) {
            int p = k * NT + tid;
            float a = 0.f, bb = 0.f, c = 0.f;
            if (p < P) { a = mp[3*p]; bb = mp[3*p+1]; c = mp[3*p+2]; }
            float x = R1.r[0]*a + R1.r[1]*bb + R1.r[2]*c;
            float y = R1.r[3]*a + R1.r[4]*bb + R1.r[5]*c;
            float z = R1.r[6]*a + R1.r[7]*bb + R1.r[8]*c;
            Ax[k] = splat2(-2.f*x); Ay[k] = splat2(-2.f*y); Az[k] = splat2(-2.f*z);
            n1v[k] = x*x + y*y + z*z;
        }

        const float INF = 3.4028235e38f;
        float m0[PPT], m1[PPT];
        #pragma unroll
        for (int k = 0; k < PPT; k++) { m0[k] = INF; m1[k] = INF; }

        const double2* __restrict__ pA = (const double2*)sA;
        const double2* __restrict__ pB = (const double2*)sB;
        #pragma unroll 2
        for (int j = 0; j < npr; j++) {
            double2 v1 = pA[j];
            double2 v2 = pB[j];
            #pragma unroll
            for (int k = 0; k < PPT; k++) {
                double t = ffma2(Ax[k], v1.x, ffma2(Ay[k], v1.y, ffma2(Az[k], v2.x, v2.y)));
                m0[k] = fminf(m0[k], lo32(t));
                m1[k] = fminf(m1[k], hi32(t));
            }
        }

        #pragma unroll
        for (int k = 0; k < PPT; k++) {
            int p = k * NT + tid;
            if (p < P) {
                float d = n1v[k] + fminf(m0[k], m1[k]);
                atomicMax(&g_keys[(size_t)b * P + p], kk_of(d));
            }
        }
        __threadfence();

        // per-batch completion: last of S chunk-items finalizes this batch inline
        if (tid == 0)
            s_last = (atomicAdd(&g_bdone[b], 1u) == (unsigned)(S - 1)) ? 1 : 0;
        __syncthreads();

        if (s_last) {
            double v = 0.0;
            #pragma unroll
            for (int k = 0; k < PPT; k++) {
                int p = k * NT + tid;
                if (p < P) {
                    size_t idx = (size_t)b * P + p;
                    unsigned int kk = g_keys[idx];
                    g_keys[idx] = 0u;                    // reset for next replay
                    v += (double)fmaxf(0.5f * f_of_kk(kk) - MARGIN, 0.f);
                }
            }
            #pragma unroll
            for (int off = 16; off > 0; off >>= 1)
                v += __shfl_down_sync(0xFFFFFFFFu, v, off);
            if (lane == 0) swarp[wid] = v;
            __syncthreads();
            if (tid == 0) {
                double bsum = 0.0;
                #pragma unroll
                for (int w = 0; w < NT / 32; w++) bsum += swarp[w];
                ll_acc += (long long)llrint(bsum * FIXED_SCALE);
                g_bdone[b] = 0u;                         // reset for next replay
            }
        }
    }

    // ---- CTA exit: contribute, then last CTA publishes & resets ----
    if (tid == 0) {
        if (ll_acc != 0)
            atomicAdd((unsigned long long*)&g_acc, (unsigned long long)ll_acc);
        __threadfence();
        unsigned int prev = atomicAdd(&g_count, 1u);
        if (prev == gridDim.x - 1) {
            long long acc = (long long)atomicAdd((unsigned long long*)&g_acc, 0ull);
            out[0] = (float)(((double)acc / FIXED_SCALE) / ((double)B * (double)P));
            g_acc  = 0;
            g_count = 0;
            g_work  = 0;
            __threadfence();
        }
    }
}

extern "C" void kernel_launch(void* const* d_in, const int* in_sizes, int n_in,
                              void* d_out, int out_size)
{
    const float* poses_pred   = (const float*)d_in[0];
    const float* poses_target = (const float*)d_in[1];
    const int*   poses_labels = (const int*)d_in[2];
    const float* points       = (const float*)d_in[3];
    const int*   symmetry     = (const int*)d_in[4];
    float* out = (float*)d_out;

    const int B = in_sizes[2];                 // labels: [B]
    const int C = in_sizes[4];                 // symmetry: [C]
    const int P = in_sizes[3] / (C * 3);       // points: [C,P,3]
    const int S = (P + QC - 1) / QC;           // q-chunks per batch
    const int total_items = B * S;

    add_loss_kernel<<<NCTAS, NT>>>(poses_pred, poses_target, poses_labels,
                                   points, symmetry, out, B, C, P, S, total_items);
}

// round 12
// speedup vs baseline: 1.7364x; 1.0024x over previous
#include <cuda_runtime.h>
#include <cuda_bf16.h>

#define NT 128              // threads per CTA
#define QC 64               // q's per work item
#define NPAIR (QC / 2)      // 32 q-pairs in shared
#define PPT 4               // points per thread (128*4 = 512 = half of P)
#define PHALF 512           // points per item
#define SUBS 32             // items per batch: 2 p-halves x 16 q-chunks
#define NCTAS 1184          // 8 CTAs/SM persistent
#define MARGIN 0.01f
#define FIXED_SCALE 4294967296.0
#define MAXBP (128 * 1024)
#define MAXB 1024
#define SYMF 0x10000

// Exact, order-independent state. Zero-init at load; every piece is reset by
// its consumer, so graph replays always start clean.
__device__ unsigned int g_keys[MAXBP];   // per-(b,p) min key; 0 == +inf
__device__ unsigned int g_bdone[MAXB];   // per-batch completed sym items
__device__ long long    g_acc;           // fixed-point deterministic loss sum
__device__ unsigned int g_count;         // CTA completion counter
__device__ unsigned int g_work;          // work queue head

struct Rot { float r[9]; };

__device__ __forceinline__ Rot quat_rot(const float* __restrict__ q) {
    float s = q[0], u = q[1], v = q[2], w = q[3];
    Rot R;
    R.r[0] = 1.f - 2.f * (v * v + w * w);
    R.r[1] = 2.f * (u * v - s * w);
    R.r[2] = 2.f * (u * w + s * v);
    R.r[3] = 2.f * (u * v + s * w);
    R.r[4] = 1.f - 2.f * (u * u + w * w);
    R.r[5] = 2.f * (v * w - s * u);
    R.r[6] = 2.f * (u * w - s * v);
    R.r[7] = 2.f * (v * w + s * u);
    R.r[8] = 1.f - 2.f * (u * u + v * v);
    return R;
}

// ---- packed f32x2 helpers (Blackwell FFMA2) ----
__device__ __forceinline__ double ffma2(double a, double b, double c) {
    double d;
    asm("fma.rn.f32x2 %0, %1, %2, %3;" : "=d"(d) : "d"(a), "d"(b), "d"(c));
    return d;
}
__device__ __forceinline__ double splat2(float x) {
    double d;
    asm("mov.b64 %0, {%1, %1};" : "=d"(d) : "f"(x));
    return d;
}
__device__ __forceinline__ float lo32(double d) { return __int_as_float(__double2loint(d)); }
__device__ __forceinline__ float hi32(double d) { return __int_as_float(__double2hiint(d)); }

// monotone-DEcreasing float->uint key: max(key) == min(float); key 0 == +inf
__device__ __forceinline__ unsigned int kk_of(float f) {
    unsigned int u = __float_as_uint(f);
    unsigned int k = (u & 0x80000000u) ? ~u : (u | 0x80000000u);
    return ~k;
}
__device__ __forceinline__ float f_of_kk(unsigned int kk) {
    unsigned int k = ~kk;
    unsigned int u = (k & 0x80000000u) ? (k ^ 0x80000000u) : ~k;
    return __uint_as_float(u);
}

__global__ void __launch_bounds__(NT, 8)
add_loss_kernel(const float* __restrict__ poses_pred,
                const float* __restrict__ poses_target,
                const int*   __restrict__ labels,
                const float* __restrict__ points,
                const int*   __restrict__ symmetry,
                float* __restrict__ out,
                int B, int C, int P, int total_items)
{
    __shared__ float4 sA[NPAIR];          // (x_2j, x_2j+1, y_2j, y_2j+1)
    __shared__ float4 sB[NPAIR];          // (z_2j, z_2j+1, n2_2j, n2_2j+1)
    __shared__ int    s_info[MAXB];       // -1 = skip; else label | (sym?SYMF:0)
    __shared__ double swarp[NT / 32];
    __shared__ int    s_item;
    __shared__ int    s_last;

    const int tid  = threadIdx.x;
    const int lane = tid & 31;
    const int wid  = tid >> 5;

    // one-time per-CTA label/symmetry table (kills per-item dependent LDGs)
    for (int i = tid; i < B; i += NT) {
        int l = labels[i];
        s_info[i] = (l <= 0) ? -1 : (symmetry[l] > 0 ? (l | SYMF) : l);
    }
    __syncthreads();

    long long ll_acc = 0;                 // tid 0 only

    for (;;) {
        if (tid == 0) s_item = (int)atomicAdd(&g_work, 1u);
        __syncthreads();
        const int item = s_item;
        if (item >= total_items) break;

        const int b   = item >> 5;        // item / SUBS
        const int sub = item & 31;
        const int pc  = sub >> 4;         // p-half (0/1)
        const int yc  = sub & 15;         // q-chunk

        const int info = s_info[b];
        if (info < 0) continue;
        const int  label = info & 0xFFFF;
        const bool sym   = (info & SYMF) != 0;

        const float* mp = points + (size_t)label * P * 3;
        Rot R1 = quat_rot(poses_pred   + ((size_t)b * C + label) * 4);
        Rot R2 = quat_rot(poses_target + ((size_t)b * C + label) * 4);

        if (!sym) {
            if (yc != 0) continue;        // ADD: only yc==0 items (both p-halves)
            double v = 0.0;
            #pragma unroll
            for (int k = 0; k < PPT; k++) {
                int p = pc * PHALF + k * NT + tid;
                if (p < P) {
                    float a = mp[3*p], bb = mp[3*p+1], c = mp[3*p+2];
                    float x1x = R1.r[0]*a + R1.r[1]*bb + R1.r[2]*c;
                    float x1y = R1.r[3]*a + R1.r[4]*bb + R1.r[5]*c;
                    float x1z = R1.r[6]*a + R1.r[7]*bb + R1.r[8]*c;
                    float x2x = R2.r[0]*a + R2.r[1]*bb + R2.r[2]*c;
                    float x2y = R2.r[3]*a + R2.r[4]*bb + R2.r[5]*c;
                    float x2z = R2.r[6]*a + R2.r[7]*bb + R2.r[8]*c;
                    float dx = x1x - x2x, dy = x1y - x2y, dz = x1z - x2z;
                    float d = dx*dx + dy*dy + dz*dz;
                    v += (double)fmaxf(0.5f * d - MARGIN, 0.f);
                }
            }
            #pragma unroll
            for (int off = 16; off > 0; off >>= 1)
                v += __shfl_down_sync(0xFFFFFFFFu, v, off);
            if (lane == 0) swarp[wid] = v;
            __syncthreads();
            if (tid == 0) {
                double bsum = 0.0;
                #pragma unroll
                for (int w = 0; w < NT / 32; w++) bsum += swarp[w];
                ll_acc += (long long)llrint(bsum * FIXED_SCALE);
            }
            continue;
        }

        // ---- ADD-S item: q-range [yc*QC, +QC) x p-half [pc*512, +512) ----
        const int q0 = yc * QC;
        const int npr = min(NPAIR, (P - q0) >> 1);
        if (tid < npr) {
            int j = tid;
            int qa = q0 + 2 * j, qb = qa + 1;
            float a0 = mp[3*qa], b0 = mp[3*qa+1], c0 = mp[3*qa+2];
            float a1 = mp[3*qb], b1 = mp[3*qb+1], c1 = mp[3*qb+2];
            float x0 = R2.r[0]*a0 + R2.r[1]*b0 + R2.r[2]*c0;
            float y0 = R2.r[3]*a0 + R2.r[4]*b0 + R2.r[5]*c0;
            float z0 = R2.r[6]*a0 + R2.r[7]*b0 + R2.r[8]*c0;
            float x1 = R2.r[0]*a1 + R2.r[1]*b1 + R2.r[2]*c1;
            float y1 = R2.r[3]*a1 + R2.r[4]*b1 + R2.r[5]*c1;
            float z1 = R2.r[6]*a1 + R2.r[7]*b1 + R2.r[8]*c1;
            sA[j] = make_float4(x0, x1, y0, y1);
            sB[j] = make_float4(z0, z1,
                                x0*x0 + y0*y0 + z0*z0,
                                x1*x1 + y1*y1 + z1*z1);
        }
        __syncthreads();

        float  n1v[PPT];
        double Ax[PPT], Ay[PPT], Az[PPT];
        #pragma unroll
        for (int k = 0; k < PPT; k++) {
            int p = pc * PHALF + k * NT + tid;
            float a = 0.f, bb = 0.f, c = 0.f;
            if (p < P) { a = mp[3*p]; bb = mp[3*p+1]; c = mp[3*p+2]; }
            float x = R1.r[0]*a + R1.r[1]*bb + R1.r[2]*c;
            float y = R1.r[3]*a + R1.r[4]*bb + R1.r[5]*c;
            float z = R1.r[6]*a + R1.r[7]*bb + R1.r[8]*c;
            Ax[k] = splat2(-2.f*x); Ay[k] = splat2(-2.f*y); Az[k] = splat2(-2.f*z);
            n1v[k] = x*x + y*y + z*z;
        }

        const float INF = 3.4028235e38f;
        float m0[PPT], m1[PPT];
        #pragma unroll
        for (int k = 0; k < PPT; k++) { m0[k] = INF; m1[k] = INF; }

        const double2* __restrict__ pA = (const double2*)sA;
        const double2* __restrict__ pB = (const double2*)sB;
        #pragma unroll 4
        for (int j = 0; j < npr; j++) {
            double2 v1 = pA[j];
            double2 v2 = pB[j];
            #pragma unroll
            for (int k = 0; k < PPT; k++) {
                double t = ffma2(Ax[k], v1.x, ffma2(Ay[k], v1.y, ffma2(Az[k], v2.x, v2.y)));
                m0[k] = fminf(m0[k], lo32(t));
                m1[k] = fminf(m1[k], hi32(t));
            }
        }

        #pragma unroll
        for (int k = 0; k < PPT; k++) {
            int p = pc * PHALF + k * NT + tid;
            if (p < P) {
                float d = n1v[k] + fminf(m0[k], m1[k]);
                atomicMax(&g_keys[(size_t)b * P + p], kk_of(d));
            }
        }
        __threadfence();

        // per-batch completion: last of SUBS sym items finalizes inline
        if (tid == 0)
            s_last = (atomicAdd(&g_bdone[b], 1u) == (unsigned)(SUBS - 1)) ? 1 : 0;
        __syncthreads();

        if (s_last) {
            double v = 0.0;
            for (int p = tid; p < P; p += NT) {
                size_t idx = (size_t)b * P + p;
                unsigned int kk = g_keys[idx];
                g_keys[idx] = 0u;                        // reset for next replay
                v += (double)fmaxf(0.5f * f_of_kk(kk) - MARGIN, 0.f);
            }
            #pragma unroll
            for (int off = 16; off > 0; off >>= 1)
                v += __shfl_down_sync(0xFFFFFFFFu, v, off);
            if (lane == 0) swarp[wid] = v;
            __syncthreads();
            if (tid == 0) {
                double bsum = 0.0;
                #pragma unroll
                for (int w = 0; w < NT / 32; w++) bsum += swarp[w];
                ll_acc += (long long)llrint(bsum * FIXED_SCALE);
                g_bdone[b] = 0u;                         // reset for next replay
            }
        }
    }

    // ---- CTA exit: contribute, then last CTA publishes & resets ----
    if (tid == 0) {
        if (ll_acc != 0)
            atomicAdd((unsigned long long*)&g_acc, (unsigned long long)ll_acc);
        __threadfence();
        unsigned int prev = atomicAdd(&g_count, 1u);
        if (prev == gridDim.x - 1) {
            long long acc = (long long)atomicAdd((unsigned long long*)&g_acc, 0ull);
            out[0] = (float)(((double)acc / FIXED_SCALE) / ((double)B * (double)P));
            g_acc  = 0;
            g_count = 0;
            g_work  = 0;
            __threadfence();
        }
    }
}

extern "C" void kernel_launch(void* const* d_in, const int* in_sizes, int n_in,
                              void* d_out, int out_size)
{
    const float* poses_pred   = (const float*)d_in[0];
    const float* poses_target = (const float*)d_in[1];
    const int*   poses_labels = (const int*)d_in[2];
    const float* points       = (const float*)d_in[3];
    const int*   symmetry     = (const int*)d_in[4];
    float* out = (float*)d_out;

    const int B = in_sizes[2];                 // labels: [B]
    const int C = in_sizes[4];                 // symmetry: [C]
    const int P = in_sizes[3] / (C * 3);       // points: [C,P,3]
    const int total_items = B * SUBS;          // 2 p-halves x 16 q-chunks

    add_loss_kernel<<<NCTAS, NT>>>(poses_pred, poses_target, poses_labels,
                                   points, symmetry, out, B, C, P, total_items);
}

// round 13
// speedup vs baseline: 1.9078x; 1.0987x over previous
#include <cuda_runtime.h>
#include <cuda_bf16.h>

#define NT 128              // threads per CTA
#define QC 64               // q's per CTA (grid.y = P/QC chunks)
#define NPAIR (QC / 2)      // 32 q-pairs in shared
#define PPT 8               // points per thread (128*8 = 1024 = P)
#define MARGIN 0.01f
#define FIXED_SCALE 4294967296.0
#define MAXBP (128 * 1024)
#define MAXB 1024

// Exact, order-independent state. Zero-init at load; every piece is reset by
// its consumer, so graph replays always start clean.
__device__ unsigned int g_keys[MAXBP];   // per-(b,p) min key; 0 == +inf
__device__ unsigned int g_bdone[MAXB];   // per-batch completed sym chunks
__device__ long long    g_acc;           // fixed-point deterministic loss sum
__device__ unsigned int g_count;         // CTA completion counter

struct Rot { float r[9]; };

__device__ __forceinline__ Rot quat_rot(const float* __restrict__ q) {
    float s = q[0], u = q[1], v = q[2], w = q[3];
    Rot R;
    R.r[0] = 1.f - 2.f * (v * v + w * w);
    R.r[1] = 2.f * (u * v - s * w);
    R.r[2] = 2.f * (u * w + s * v);
    R.r[3] = 2.f * (u * v + s * w);
    R.r[4] = 1.f - 2.f * (u * u + w * w);
    R.r[5] = 2.f * (v * w - s * u);
    R.r[6] = 2.f * (u * w - s * v);
    R.r[7] = 2.f * (v * w + s * u);
    R.r[8] = 1.f - 2.f * (u * u + v * v);
    return R;
}

// ---- packed f32x2 helpers (Blackwell FFMA2) ----
__device__ __forceinline__ double ffma2(double a, double b, double c) {
    double d;
    asm("fma.rn.f32x2 %0, %1, %2, %3;" : "=d"(d) : "d"(a), "d"(b), "d"(c));
    return d;
}
__device__ __forceinline__ double splat2(float x) {
    double d;
    asm("mov.b64 %0, {%1, %1};" : "=d"(d) : "f"(x));
    return d;
}
__device__ __forceinline__ float lo32(double d) { return __int_as_float(__double2loint(d)); }
__device__ __forceinline__ float hi32(double d) { return __int_as_float(__double2hiint(d)); }

// monotone-DEcreasing float->uint key: max(key) == min(float); key 0 == +inf
__device__ __forceinline__ unsigned int kk_of(float f) {
    unsigned int u = __float_as_uint(f);
    unsigned int k = (u & 0x80000000u) ? ~u : (u | 0x80000000u);
    return ~k;
}
__device__ __forceinline__ float f_of_kk(unsigned int kk) {
    unsigned int k = ~kk;
    unsigned int u = (k & 0x80000000u) ? (k ^ 0x80000000u) : ~k;
    return __uint_as_float(u);
}

__global__ void __launch_bounds__(NT)
add_loss_kernel(const float* __restrict__ poses_pred,
                const float* __restrict__ poses_target,
                const int*   __restrict__ labels,
                const float* __restrict__ points,
                const int*   __restrict__ symmetry,
                float* __restrict__ out,
                int B, int C, int P, int S)
{
    __shared__ float4 sA[NPAIR];          // (x_2j, x_2j+1, y_2j, y_2j+1)
    __shared__ float4 sB[NPAIR];          // (z_2j, z_2j+1, n2_2j, n2_2j+1)
    __shared__ double swarp[NT / 32];
    __shared__ int    s_last;

    const int b    = blockIdx.x;
    const int yc   = blockIdx.y;
    const int tid  = threadIdx.x;
    const int lane = tid & 31;
    const int wid  = tid >> 5;
    const unsigned int total_ctas = gridDim.x * gridDim.y;

    long long ll_acc = 0;                 // tid 0 only

    const int label = labels[b];
    if (label > 0) {
        const bool sym = symmetry[label] > 0;
        const float* mp = points + (size_t)label * P * 3;

        if (!sym) {
            if (yc == 0) {
                // ADD: whole batch handled by this one CTA, 8 pts/thread
                Rot R1 = quat_rot(poses_pred   + ((size_t)b * C + label) * 4);
                Rot R2 = quat_rot(poses_target + ((size_t)b * C + label) * 4);
                double v = 0.0;
                #pragma unroll
                for (int k = 0; k < PPT; k++) {
                    int p = k * NT + tid;
                    if (p < P) {
                        float a = mp[3*p], bb = mp[3*p+1], c = mp[3*p+2];
                        float x1x = R1.r[0]*a + R1.r[1]*bb + R1.r[2]*c;
                        float x1y = R1.r[3]*a + R1.r[4]*bb + R1.r[5]*c;
                        float x1z = R1.r[6]*a + R1.r[7]*bb + R1.r[8]*c;
                        float x2x = R2.r[0]*a + R2.r[1]*bb + R2.r[2]*c;
                        float x2y = R2.r[3]*a + R2.r[4]*bb + R2.r[5]*c;
                        float x2z = R2.r[6]*a + R2.r[7]*bb + R2.r[8]*c;
                        float dx = x1x - x2x, dy = x1y - x2y, dz = x1z - x2z;
                        float d = dx*dx + dy*dy + dz*dz;
                        v += (double)fmaxf(0.5f * d - MARGIN, 0.f);
                    }
                }
                #pragma unroll
                for (int off = 16; off > 0; off >>= 1)
                    v += __shfl_down_sync(0xFFFFFFFFu, v, off);
                if (lane == 0) swarp[wid] = v;
                __syncthreads();
                if (tid == 0) {
                    double bsum = 0.0;
                    #pragma unroll
                    for (int w = 0; w < NT / 32; w++) bsum += swarp[w];
                    ll_acc += (long long)llrint(bsum * FIXED_SCALE);
                }
            }
        } else {
            // ---- ADD-S: q-range [yc*QC, +QC) x ALL P points ----
            Rot R1 = quat_rot(poses_pred   + ((size_t)b * C + label) * 4);
            Rot R2 = quat_rot(poses_target + ((size_t)b * C + label) * 4);

            const int q0 = yc * QC;
            const int npr = min(NPAIR, (P - q0) >> 1);
            if (tid < npr) {
                int j = tid;
                int qa = q0 + 2 * j, qb = qa + 1;
                float a0 = mp[3*qa], b0 = mp[3*qa+1], c0 = mp[3*qa+2];
                float a1 = mp[3*qb], b1 = mp[3*qb+1], c1 = mp[3*qb+2];
                float x0 = R2.r[0]*a0 + R2.r[1]*b0 + R2.r[2]*c0;
                float y0 = R2.r[3]*a0 + R2.r[4]*b0 + R2.r[5]*c0;
                float z0 = R2.r[6]*a0 + R2.r[7]*b0 + R2.r[8]*c0;
                float x1 = R2.r[0]*a1 + R2.r[1]*b1 + R2.r[2]*c1;
                float y1 = R2.r[3]*a1 + R2.r[4]*b1 + R2.r[5]*c1;
                float z1 = R2.r[6]*a1 + R2.r[7]*b1 + R2.r[8]*c1;
                sA[j] = make_float4(x0, x1, y0, y1);
                sB[j] = make_float4(z0, z1,
                                    x0*x0 + y0*y0 + z0*z0,
                                    x1*x1 + y1*y1 + z1*z1);
            }
            __syncthreads();

            float  n1v[PPT];
            double Ax[PPT], Ay[PPT], Az[PPT];
            #pragma unroll
            for (int k = 0; k < PPT; k++) {
                int p = k * NT + tid;
                float a = 0.f, bb = 0.f, c = 0.f;
                if (p < P) { a = mp[3*p]; bb = mp[3*p+1]; c = mp[3*p+2]; }
                float x = R1.r[0]*a + R1.r[1]*bb + R1.r[2]*c;
                float y = R1.r[3]*a + R1.r[4]*bb + R1.r[5]*c;
                float z = R1.r[6]*a + R1.r[7]*bb + R1.r[8]*c;
                Ax[k] = splat2(-2.f*x); Ay[k] = splat2(-2.f*y); Az[k] = splat2(-2.f*z);
                n1v[k] = x*x + y*y + z*z;
            }

            const float INF = 3.4028235e38f;
            float m0[PPT], m1[PPT];
            #pragma unroll
            for (int k = 0; k < PPT; k++) { m0[k] = INF; m1[k] = INF; }

            const double2* __restrict__ pA = (const double2*)sA;
            const double2* __restrict__ pB = (const double2*)sB;
            #pragma unroll 8
            for (int j = 0; j < npr; j++) {
                double2 v1 = pA[j];
                double2 v2 = pB[j];
                #pragma unroll
                for (int k = 0; k < PPT; k++) {
                    double t = ffma2(Ax[k], v1.x, ffma2(Ay[k], v1.y, ffma2(Az[k], v2.x, v2.y)));
                    m0[k] = fminf(m0[k], lo32(t));
                    m1[k] = fminf(m1[k], hi32(t));
                }
            }

            #pragma unroll
            for (int k = 0; k < PPT; k++) {
                int p = k * NT + tid;
                if (p < P) {
                    float d = n1v[k] + fminf(m0[k], m1[k]);
                    atomicMax(&g_keys[(size_t)b * P + p], kk_of(d));
                }
            }
            __threadfence();
            __syncthreads();   // ALL threads' maxes fenced before the counter bump

            // last of S chunk-CTAs for this batch finalizes inline
            if (tid == 0)
                s_last = (atomicAdd(&g_bdone[b], 1u) == (unsigned)(S - 1)) ? 1 : 0;
            __syncthreads();

            if (s_last) {
                double v = 0.0;
                #pragma unroll
                for (int k = 0; k < PPT; k++) {
                    int p = k * NT + tid;
                    if (p < P) {
                        size_t idx = (size_t)b * P + p;
                        unsigned int kk = g_keys[idx];
                        g_keys[idx] = 0u;                // reset for next replay
                        v += (double)fmaxf(0.5f * f_of_kk(kk) - MARGIN, 0.f);
                    }
                }
                #pragma unroll
                for (int off = 16; off > 0; off >>= 1)
                    v += __shfl_down_sync(0xFFFFFFFFu, v, off);
                if (lane == 0) swarp[wid] = v;
                __syncthreads();
                if (tid == 0) {
                    double bsum = 0.0;
                    #pragma unroll
                    for (int w = 0; w < NT / 32; w++) bsum += swarp[w];
                    ll_acc += (long long)llrint(bsum * FIXED_SCALE);
                    g_bdone[b] = 0u;                     // reset for next replay
                }
            }
        }
    }

    // ---- CTA exit: contribute, then last CTA publishes & resets ----
    if (tid == 0) {
        if (ll_acc != 0)
            atomicAdd((unsigned long long*)&g_acc, (unsigned long long)ll_acc);
        __threadfence();
        unsigned int prev = atomicAdd(&g_count, 1u);
        if (prev == total_ctas - 1) {
            long long acc = (long long)atomicAdd((unsigned long long*)&g_acc, 0ull);
            out[0] = (float)(((double)acc / FIXED_SCALE) / ((double)B * (double)P));
            g_acc  = 0;
            g_count = 0;
            __threadfence();
        }
    }
}

extern "C" void kernel_launch(void* const* d_in, const int* in_sizes, int n_in,
                              void* d_out, int out_size)
{
    const float* poses_pred   = (const float*)d_in[0];
    const float* poses_target = (const float*)d_in[1];
    const int*   poses_labels = (const int*)d_in[2];
    const float* points       = (const float*)d_in[3];
    const int*   symmetry     = (const int*)d_in[4];
    float* out = (float*)d_out;

    const int B = in_sizes[2];                 // labels: [B]
    const int C = in_sizes[4];                 // symmetry: [C]
    const int P = in_sizes[3] / (C * 3);       // points: [C,P,3]
    const int S = (P + QC - 1) / QC;           // q-chunks per batch

    dim3 grid(B, S);
    add_loss_kernel<<<grid, NT>>>(poses_pred, poses_target, poses_labels,
                                  points, symmetry, out, B, C, P, S);
}